// round 6
// baseline (speedup 1.0000x reference)
#include <cuda_runtime.h>
#include <cuda_bf16.h>
#include <math_constants.h>

// Problem constants (fixed by the benchmark)
#define BB 2
#define LL 2048
#define HH 8
#define DD 64
#define UU 80
#define SS 80
#define BHN (BB*HH)
#define SPLIT 16
#define CHUNK (LL/SPLIT)      // 128 keys per split block
#define UST 8                 // u-stride for winner loop

// Sample kernel tiling
#define LT 256                // l rows per block
#define NLT (LL/LT)           // 8 l-tiles
#define KT 256                // keys per smem K tile
#define NKT (LL/KT)           // 8 key tiles
#define NPAIR (LT*SS)         // 20480 pairs per block
#define BLKS_PER_BH NLT       // 8 sample blocks per (b,h)
// dynamic smem: Qs(64KB) + Ks(64KB) + pairs(40KB)
#define SMP_SMEM (LT*DD*4 + KT*DD*4 + NPAIR*2)

// Scratch (device globals; zero-initialized at module load)
__device__ float g_M[BB*HH*LL];           // sparsity measure M[b,h,l]
__device__ float g_vmean[BHN*DD];         // V column sums (atomic), re-zeroed after use
__device__ int   g_cb[BHN];               // per-bh completion counter (self-reset)
__device__ int   g_cu[BHN*UU];            // per-(bh,u) split counter (self-reset)
__device__ int   g_nw[BHN];               // winners per (b,h)
__device__ int   g_wl[BHN*UU];            // winner: source token l
__device__ int   g_wj[BHN*UU];            // winner: output slot j
__device__ float g_pmax[BHN*UU*SPLIT];    // split-softmax partial max
__device__ float g_psum[BHN*UU*SPLIT];    // split-softmax partial sum(exp)
__device__ float g_pv  [BHN*UU*SPLIT*DD]; // split partial (unnormalized) PV

// monotone float<->uint order encoding (exact compares)
__device__ __forceinline__ unsigned fenc(float x) {
    unsigned b = __float_as_uint(x);
    return (b & 0x80000000u) ? ~b : (b | 0x80000000u);
}
__device__ __forceinline__ float fdec(unsigned u) {
    unsigned b = (u & 0x80000000u) ? (u & 0x7FFFFFFFu) : ~u;
    return __uint_as_float(b);
}

// ---------------------------------------------------------------------------
// Kernel 1: SMEM-routed sampled scores + V sums + (last block per bh) top-80.
// Block = (l-tile of 256 rows, bh), 512 threads, 1 CTA/SM, 128 blocks.
//  - stage Q tile in smem; build in-smem CSR pair list (l,j) bucketed by K tile
//  - per K tile: stage 64KB K tile, 64 groups of 8 lanes process a flat chunk
//    of pairs (K row read = two conflict-free 128B-line LDS.128 per lane set,
//    Q cached in regs across same-l runs); exact max via smem atomicMax on
//    encoded uint, sum via smem atomicAdd.
//  - last block per bh runs radix-select + bitonic top-80 (jax.lax.top_k
//    semantics), winner replay, V_mean broadcast fill.
// ---------------------------------------------------------------------------
__global__ void __launch_bounds__(512, 1)
k_sample_topk(const float* __restrict__ Q, const float* __restrict__ K,
              const float* __restrict__ V, const int* __restrict__ idx,
              float* __restrict__ out) {
    extern __shared__ float dsm[];
    float* Qs = dsm;                                   // LT*64 floats
    float* Ks = dsm + LT*DD;                           // KT*64 floats
    unsigned short* pairs = (unsigned short*)(dsm + LT*DD + KT*DD); // NPAIR u16
    int* cnt = (int*)Ks;                               // build-phase overlay on Ks

    __shared__ unsigned smaxU[LT];
    __shared__ float    ssum[LT];
    __shared__ float    vtmp[8][DD];
    __shared__ int      tstart[NKT+1];
    __shared__ int      tot[NKT];
    __shared__ int      isLast;
    // top-k state (last block per bh only)
    __shared__ unsigned su[LL];
    __shared__ int hist[256];
    __shared__ int scnt2[2];
    __shared__ unsigned long long keys[128];
    __shared__ int eqbuf[256];
    __shared__ int cgt, ceq;
    __shared__ int stop[UU];
    __shared__ int win[UU];
    __shared__ float mean[DD];

    int t = threadIdx.x, lane = t & 31, warp = t >> 5;
    int lt = blockIdx.x, bh = blockIdx.y;
    int b = bh >> 3, h = bh & 7;
    int l0 = lt * LT;

    // ---- stage Q tile (coalesced float4) ----
    #pragma unroll
    for (int e = t; e < LT*16; e += 512) {
        int row = e >> 4, c4 = e & 15;
        ((float4*)Qs)[row*16 + c4] =
            *(const float4*)(Q + (((size_t)b*LL + l0 + row)*HH + h)*DD + c4*4);
    }

    // ---- V partial column sums for this l-tile ----
    {
        int rg = t >> 6, d = t & 63;
        float s = 0.f;
        #pragma unroll 8
        for (int l = rg; l < LT; l += 8)
            s += V[(((size_t)b*LL + l0 + l)*HH + h)*DD + d];
        vtmp[rg][d] = s;
    }

    // ---- build phase: count samples per key tile (owner thread per l) ----
    if (t < LT) {
        const int4* ir = (const int4*)(idx + (size_t)(l0 + t)*SS);
        int c[NKT];
        #pragma unroll
        for (int i = 0; i < NKT; ++i) c[i] = 0;
        #pragma unroll 5
        for (int q4 = 0; q4 < SS/4; ++q4) {
            int4 v = ir[q4];
            c[v.x >> 8]++; c[v.y >> 8]++; c[v.z >> 8]++; c[v.w >> 8]++;
        }
        #pragma unroll
        for (int i = 0; i < NKT; ++i) cnt[i*LT + t] = c[i];
        smaxU[t] = 0u;        // encodes below any real value
        ssum[t]  = 0.f;
    }
    __syncthreads();

    // finish V sums (one atomic per d)
    if (t < DD) {
        float s = vtmp[0][t] + vtmp[1][t] + vtmp[2][t] + vtmp[3][t]
                + vtmp[4][t] + vtmp[5][t] + vtmp[6][t] + vtmp[7][t];
        atomicAdd(&g_vmean[bh*DD + t], s);
    }

    // ---- exclusive scan per tile (warp w owns tile w) ----
    if (warp < NKT) {
        int base = warp*LT;
        int v[8], s = 0;
        #pragma unroll
        for (int e = 0; e < 8; ++e) { v[e] = cnt[base + lane*8 + e]; s += v[e]; }
        int pre = s;
        #pragma unroll
        for (int o = 1; o < 32; o <<= 1) {
            int x = __shfl_up_sync(0xffffffffu, pre, o);
            if (lane >= o) pre += x;
        }
        int run = pre - s;
        #pragma unroll
        for (int e = 0; e < 8; ++e) { int c = v[e]; cnt[base + lane*8 + e] = run; run += c; }
        if (lane == 31) tot[warp] = pre;
    }
    __syncthreads();
    if (t == 0) {
        tstart[0] = 0;
        for (int i = 0; i < NKT; ++i) tstart[i+1] = tstart[i] + tot[i];
    }
    __syncthreads();

    // ---- write pairs at deterministic CSR positions ----
    if (t < LT) {
        int cur[NKT];
        #pragma unroll
        for (int i = 0; i < NKT; ++i) cur[i] = tstart[i] + cnt[i*LT + t];
        const int4* ir = (const int4*)(idx + (size_t)(l0 + t)*SS);
        #pragma unroll 5
        for (int q4 = 0; q4 < SS/4; ++q4) {
            int4 v = ir[q4];
            int j;
            j = v.x; pairs[cur[j>>8]++] = (unsigned short)((t << 8) | (j & 255));
            j = v.y; pairs[cur[j>>8]++] = (unsigned short)((t << 8) | (j & 255));
            j = v.z; pairs[cur[j>>8]++] = (unsigned short)((t << 8) | (j & 255));
            j = v.w; pairs[cur[j>>8]++] = (unsigned short)((t << 8) | (j & 255));
        }
    }
    __syncthreads();

    // ---- main loop over key tiles ----
    int g = t >> 3, lg = t & 7;       // 64 groups of 8 lanes
    for (int kt = 0; kt < NKT; ++kt) {
        // stage K tile (overwrites cnt overlay; safe after pair write barrier)
        #pragma unroll
        for (int e = t; e < KT*16; e += 512) {
            int row = e >> 4, c4 = e & 15;
            ((float4*)Ks)[row*16 + c4] =
                *(const float4*)(K + (((size_t)b*LL + kt*KT + row)*HH + h)*DD + c4*4);
        }
        __syncthreads();

        int pbeg = tstart[kt], pend = tstart[kt+1];
        int n = pend - pbeg;
        int c = (n + 63) >> 6;                 // chunk per group
        int s0 = pbeg + g*c;
        int s1 = min(s0 + c, pend);
        int osteps = (c + 7) >> 3;             // uniform across warp

        int cur_l = -1;
        float4 q0v = make_float4(0,0,0,0), q1v = q0v;
        int pos = s0;
        for (int os = 0; os < osteps; ++os, pos += 8) {
            int pp = pos + lg;
            unsigned myp = (pp < s1) ? (unsigned)pairs[pp] : 0u;
            #pragma unroll
            for (int i = 0; i < 8; ++i) {
                unsigned pr = __shfl_sync(0xffffffffu, myp, i, 8);
                bool act = (pos + i < s1);     // uniform within group
                int l = pr >> 8;
                int j = pr & 255;
                if (act && l != cur_l) {
                    q0v = *(const float4*)(Qs + l*DD + lg*4);
                    q1v = *(const float4*)(Qs + l*DD + 32 + lg*4);
                    cur_l = l;
                }
                float4 k0v = *(const float4*)(Ks + j*DD + lg*4);
                float4 k1v = *(const float4*)(Ks + j*DD + 32 + lg*4);
                float p = q0v.x*k0v.x + q0v.y*k0v.y + q0v.z*k0v.z + q0v.w*k0v.w
                        + q1v.x*k1v.x + q1v.y*k1v.y + q1v.z*k1v.z + q1v.w*k1v.w;
                p += __shfl_xor_sync(0xffffffffu, p, 4);
                p += __shfl_xor_sync(0xffffffffu, p, 2);
                p += __shfl_xor_sync(0xffffffffu, p, 1);
                if (act && lg == 0) {
                    atomicMax(&smaxU[l], fenc(p));
                    atomicAdd(&ssum[l], p);
                }
            }
        }
        __syncthreads();
    }

    // ---- finalize M for this tile ----
    if (t < LT)
        g_M[bh*LL + l0 + t] = fdec(smaxU[t]) - ssum[t] * (1.0f/(float)LL);

    // ---- completion protocol: last block of this bh runs top-k inline ----
    __threadfence();
    __syncthreads();
    if (t == 0) {
        int old = atomicAdd(&g_cb[bh], 1);
        isLast = (old == BLKS_PER_BH - 1);
    }
    __syncthreads();
    if (!isLast) return;
    if (t == 0) g_cb[bh] = 0;                  // self-reset for next replay

    // ======================= top-k body (last block) =======================
    if (t < DD) {
        mean[t] = g_vmean[bh*DD + t] * (1.0f/(float)LL);
        g_vmean[bh*DD + t] = 0.f;
    }
    for (int i = t; i < LL; i += 512) {
        unsigned bb = __float_as_uint(g_M[bh*LL + i]);
        su[i] = (bb & 0x80000000u) ? ~bb : (bb | 0x80000000u);
    }
    __syncthreads();

    // broadcast-fill all 80 output rows with V_mean (winners overwritten later)
    for (int e = t; e < UU*DD; e += 512) {
        int j = e >> 6, d = e & 63;
        out[(((size_t)b*UU + j)*HH + h)*DD + d] = mean[d];
    }

    // 4-pass byte radix: T = 80th-largest transformed value
    unsigned prefix = 0, prefmask = 0;
    int need = UU;
    for (int pass = 0; pass < 4; ++pass) {
        int shift = 24 - pass*8;
        if (t < 256) hist[t] = 0;
        __syncthreads();
        for (int i = t; i < LL; i += 512) {
            unsigned u = su[i];
            if ((u & prefmask) == prefix) atomicAdd(&hist[(u >> shift) & 0xFF], 1);
        }
        __syncthreads();
        if (t < 32) {
            int base = 255 - t*8;
            int s = 0;
            #pragma unroll
            for (int e = 0; e < 8; ++e) s += hist[base - e];
            int pre = s;
            #pragma unroll
            for (int o = 1; o < 32; o <<= 1) {
                int v = __shfl_up_sync(0xffffffffu, pre, o);
                if (lane >= o) pre += v;
            }
            int excl = pre - s;
            if (excl < need && need <= pre) {
                int acc = excl;
                #pragma unroll
                for (int e = 0; e < 8; ++e) {
                    int hb = hist[base - e];
                    if (acc + hb >= need) { scnt2[0] = base - e; scnt2[1] = acc; break; }
                    acc += hb;
                }
            }
        }
        __syncthreads();
        prefix |= ((unsigned)scnt2[0]) << shift;
        prefmask |= 0xFFu << shift;
        need -= scnt2[1];
        __syncthreads();
    }
    unsigned T = prefix;

    if (t == 0) { cgt = 0; ceq = 0; }
    __syncthreads();
    for (int i = t; i < LL; i += 512) {
        unsigned u = su[i];
        if (u > T) {
            int p = atomicAdd(&cgt, 1);
            keys[p] = ((unsigned long long)u << 32) | (unsigned)(~i);
        } else if (u == T) {
            int p = atomicAdd(&ceq, 1);
            if (p < 256) eqbuf[p] = i;
        }
    }
    __syncthreads();
    if (t == 0) {
        int base = cgt;
        int ce = min(ceq, 256);
        for (int k = 0; k < need; ++k) {
            int mi = 0x7fffffff, mp = -1;
            for (int e = 0; e < ce; ++e)
                if (eqbuf[e] < mi) { mi = eqbuf[e]; mp = e; }
            keys[base + k] = ((unsigned long long)T << 32) | (unsigned)(~mi);
            eqbuf[mp] = 0x7fffffff;
        }
    }
    if (t < 128 && t >= UU) keys[t] = 0ULL;
    __syncthreads();

    // bitonic sort, 128 elements, descending (=> value desc, index asc)
    for (int ksz = 2; ksz <= 128; ksz <<= 1) {
        for (int jst = ksz >> 1; jst > 0; jst >>= 1) {
            __syncthreads();
            if (t < 128) {
                int ixj = t ^ jst;
                if (ixj > t) {
                    unsigned long long a = keys[t], cc = keys[ixj];
                    bool up = (t & ksz) == 0;
                    if (up ? (a < cc) : (a > cc)) { keys[t] = cc; keys[ixj] = a; }
                }
            }
        }
    }
    __syncthreads();

    if (t < UU) {
        stop[t] = (int)(~(unsigned)(keys[t] & 0xffffffffu));
        win[t] = -1;
    }
    __syncthreads();
    if (t == 0) {
        for (int u = 0; u < UU; ++u) { int jj = min(stop[u], UU-1); win[jj] = u; }
        int n2 = 0;
        for (int jj = 0; jj < UU; ++jj) {
            if (win[jj] >= 0) {
                g_wl[bh*UU + n2] = stop[win[jj]];
                g_wj[bh*UU + n2] = jj;
                n2++;
            }
        }
        g_nw[bh] = n2;
    }
}

// ---------------------------------------------------------------------------
// Kernel 2: split-K attention partials for winner rows with last-split-block
// combine. SPLIT=16, CHUNK=128, 256 threads, grid (bh, UST, SPLIT).
// ---------------------------------------------------------------------------
__global__ void k_attn(const float* __restrict__ Q, const float* __restrict__ K,
                       const float* __restrict__ V, float* __restrict__ out) {
    int bh = blockIdx.x;
    int n = g_nw[bh];
    int b = bh >> 3, h = bh & 7;
    int sp = blockIdx.z, k0 = sp * CHUNK;

    __shared__ float q[DD];
    __shared__ float p[CHUNK];
    __shared__ float red[8];
    __shared__ float ac[4][64];
    __shared__ int lastf;
    int t = threadIdx.x, lane = t & 31, warp = t >> 5;
    int grp = lane >> 3, lg = lane & 7;

    for (int u = blockIdx.y; u < n; u += UST) {
        int l = g_wl[bh*UU + u];
        if (t < DD) q[t] = Q[(((size_t)b*LL + l)*HH + h)*DD + t];
        __syncthreads();
        float4 q0 = ((float4*)q)[lg*2];
        float4 q1 = ((float4*)q)[lg*2 + 1];

        // scores: each warp owns 16 keys, 4 per iteration (one per 8-lane group)
        float lmax = -CUDART_INF_F;
        #pragma unroll
        for (int it = 0; it < 4; ++it) {
            int kk = warp*16 + it*4 + grp;
            const float* kr = K + (((size_t)b*LL + k0 + kk)*HH + h)*DD + lg*8;
            float4 k0v = *(const float4*)kr;
            float4 k1v = *(const float4*)(kr + 4);
            float s = q0.x*k0v.x + q0.y*k0v.y + q0.z*k0v.z + q0.w*k0v.w
                    + q1.x*k1v.x + q1.y*k1v.y + q1.z*k1v.z + q1.w*k1v.w;
            s += __shfl_xor_sync(0xffffffffu, s, 4);
            s += __shfl_xor_sync(0xffffffffu, s, 2);
            s += __shfl_xor_sync(0xffffffffu, s, 1);
            s *= 0.125f;                 // 1/sqrt(64)
            if (lg == 0) p[kk] = s;
            lmax = fmaxf(lmax, s);
        }
        lmax = fmaxf(lmax, __shfl_xor_sync(0xffffffffu, lmax, 8));
        lmax = fmaxf(lmax, __shfl_xor_sync(0xffffffffu, lmax, 16));
        if (lane == 0) red[warp] = lmax;
        __syncthreads();
        if (t == 0) { float m = red[0]; for (int w = 1; w < 8; ++w) m = fmaxf(m, red[w]); red[0] = m; }
        __syncthreads();
        float m = red[0];
        __syncthreads();

        float e = 0.f;
        if (t < CHUNK) { e = __expf(p[t] - m); p[t] = e; }
        float ls = e;
        #pragma unroll
        for (int o = 16; o; o >>= 1) ls += __shfl_xor_sync(0xffffffffu, ls, o);
        if (lane == 0) red[warp] = ls;
        __syncthreads();
        float ssum = red[0]+red[1]+red[2]+red[3]+red[4]+red[5]+red[6]+red[7];

        // partial PV: 4 key-groups x 64 d-threads, coalesced V reads
        int g4 = t >> 6, d = t & 63;
        float acc = 0.f;
        #pragma unroll 8
        for (int kk = g4; kk < CHUNK; kk += 4)
            acc += p[kk] * V[(((size_t)b*LL + k0 + kk)*HH + h)*DD + d];
        ac[g4][d] = acc;
        __syncthreads();
        int base = (bh*UU + u)*SPLIT + sp;
        if (t < 64)
            g_pv[(size_t)base*DD + t] = ac[0][t] + ac[1][t] + ac[2][t] + ac[3][t];
        if (t == 0) { g_pmax[base] = m; g_psum[base] = ssum; }

        // ---- last split block for this (bh,u) combines and writes out ----
        __threadfence();
        __syncthreads();
        if (t == 0) {
            int old = atomicAdd(&g_cu[bh*UU + u], 1);
            lastf = (old == SPLIT - 1);
        }
        __syncthreads();
        if (lastf) {
            if (t == 0) g_cu[bh*UU + u] = 0;   // self-reset for replay
            if (t < 64) {
                int cb = (bh*UU + u)*SPLIT;
                float mm = -CUDART_INF_F;
                #pragma unroll
                for (int i = 0; i < SPLIT; ++i) mm = fmaxf(mm, g_pmax[cb + i]);
                float s = 0.f, pv = 0.f;
                #pragma unroll
                for (int i = 0; i < SPLIT; ++i) {
                    float w = __expf(g_pmax[cb + i] - mm);
                    s  += g_psum[cb + i] * w;
                    pv += g_pv[(size_t)(cb + i)*DD + t] * w;
                }
                int j = g_wj[bh*UU + u];
                out[(((size_t)b*UU + j)*HH + h)*DD + t] = pv / s;
            }
        }
        __syncthreads();                 // smem reuse across u iterations
    }
}

// ---------------------------------------------------------------------------
extern "C" void kernel_launch(void* const* d_in, const int* in_sizes, int n_in,
                              void* d_out, int out_size) {
    const float* Q   = (const float*)d_in[0];
    const float* K   = (const float*)d_in[1];
    const float* V   = (const float*)d_in[2];
    const int*   idx = (const int*)d_in[3];
    float* out = (float*)d_out;

    cudaFuncSetAttribute(k_sample_topk, cudaFuncAttributeMaxDynamicSharedMemorySize, SMP_SMEM);

    dim3 gs(NLT, BHN);
    k_sample_topk<<<gs, 512, SMP_SMEM>>>(Q, K, V, idx, out);
    dim3 ga(BHN, UST, SPLIT);
    k_attn<<<ga, 256>>>(Q, K, V, out);
}